// round 1
// baseline (speedup 1.0000x reference)
#include <cuda_runtime.h>
#include <cstdint>

#define HS 128
#define WS 128
#define NPIX 16384           // HS*WS
#define BATCH 8
#define CDIM 192
#define C3 576
#define HEADS 8
#define CD 24

// ---------------- scratch (device globals; no allocation allowed) ----------------
__device__ float g_qkv0[(size_t)BATCH * C3 * NPIX];     // after 1x1 conv (302 MB)
__device__ float g_v[(size_t)BATCH * CDIM * NPIX];      // v after dw conv (100 MB)
__device__ float g_G[BATCH * HEADS * CD * CD];          // q k^T gram
__device__ float g_QN[BATCH * HEADS * CD];              // sum q^2
__device__ float g_KN[BATCH * HEADS * CD];              // sum k^2
__device__ float g_M[BATCH * CDIM * CDIM];              // folded per-batch matrix

// ---------------- init: zero the reduction buffers ----------------
__global__ void init_stats_kernel() {
    int tot = BATCH * HEADS * CD * CD;
    for (int i = threadIdx.x; i < tot; i += blockDim.x) g_G[i] = 0.f;
    int tot2 = BATCH * HEADS * CD;
    for (int i = threadIdx.x; i < tot2; i += blockDim.x) { g_QN[i] = 0.f; g_KN[i] = 0.f; }
}

// ---------------- SGEMM: C[b] = A @ B[b] + bias ----------------
// MODE 0: A = w_qkv (576x192), B = x[b] (192xN), C = g_qkv0[b]
// MODE 1: A = g_M[b] (192x192), B = g_v[b] (192xN), C = out[b]
// BM=64, BN=128, BK=8, TM=TN=8, 128 threads
template<int MODE>
__global__ __launch_bounds__(128) void gemm_kernel(
    const float* __restrict__ Aext, const float* __restrict__ Bext,
    const float* __restrict__ bias, float* __restrict__ Cext)
{
    constexpr int K = CDIM;
    const int b = blockIdx.z;
    const float* Ab = (MODE == 0) ? Aext : (g_M + (size_t)b * CDIM * CDIM);
    const float* Bb = (MODE == 0) ? (Bext + (size_t)b * CDIM * NPIX)
                                  : (g_v + (size_t)b * CDIM * NPIX);
    float* Cb = (MODE == 0) ? (g_qkv0 + (size_t)b * C3 * NPIX)
                            : (Cext + (size_t)b * CDIM * NPIX);

    const int n0 = blockIdx.x * 128;
    const int m0 = blockIdx.y * 64;

    __shared__ __align__(16) float As[8][64];
    __shared__ __align__(16) float Bs[8][128];

    const int tid = threadIdx.x;
    const int tx = tid & 15;        // 0..15 -> n groups of 8
    const int ty = tid >> 4;        // 0..7  -> m groups of 8

    const int arow = tid >> 1;            // 0..63
    const int acol4 = (tid & 1) * 4;      // 0 or 4
    const int bk = tid >> 5;              // 0..3
    const int bn4 = (tid & 31) * 4;       // 0..124

    float acc[8][8];
#pragma unroll
    for (int i = 0; i < 8; i++)
#pragma unroll
        for (int j = 0; j < 8; j++) acc[i][j] = 0.f;

    for (int k0 = 0; k0 < K; k0 += 8) {
        float4 av = *(const float4*)&Ab[(size_t)(m0 + arow) * K + k0 + acol4];
        As[acol4 + 0][arow] = av.x;
        As[acol4 + 1][arow] = av.y;
        As[acol4 + 2][arow] = av.z;
        As[acol4 + 3][arow] = av.w;
        float4 bv0 = *(const float4*)&Bb[(size_t)(k0 + bk) * NPIX + n0 + bn4];
        float4 bv1 = *(const float4*)&Bb[(size_t)(k0 + bk + 4) * NPIX + n0 + bn4];
        *(float4*)&Bs[bk][bn4] = bv0;
        *(float4*)&Bs[bk + 4][bn4] = bv1;
        __syncthreads();
#pragma unroll
        for (int kk = 0; kk < 8; kk++) {
            float ra[8], rb[8];
            *(float4*)&ra[0] = *(const float4*)&As[kk][ty * 8];
            *(float4*)&ra[4] = *(const float4*)&As[kk][ty * 8 + 4];
            *(float4*)&rb[0] = *(const float4*)&Bs[kk][tx * 8];
            *(float4*)&rb[4] = *(const float4*)&Bs[kk][tx * 8 + 4];
#pragma unroll
            for (int i = 0; i < 8; i++)
#pragma unroll
                for (int j = 0; j < 8; j++) acc[i][j] += ra[i] * rb[j];
        }
        __syncthreads();
    }

#pragma unroll
    for (int i = 0; i < 8; i++) {
        int o = m0 + ty * 8 + i;
        float bo = bias[o];
        size_t base = (size_t)o * NPIX + n0 + tx * 8;
        float4 v0 = make_float4(acc[i][0] + bo, acc[i][1] + bo, acc[i][2] + bo, acc[i][3] + bo);
        float4 v1 = make_float4(acc[i][4] + bo, acc[i][5] + bo, acc[i][6] + bo, acc[i][7] + bo);
        *(float4*)&Cb[base] = v0;
        *(float4*)&Cb[base + 4] = v1;
    }
}

// ---------------- dw conv (3x3, groups) + Gram/norm reduction + v write ----------------
// grid: (128 pixel tiles of 8 rows x 16 cols, HEADS, BATCH), 128 threads
__global__ __launch_bounds__(128) void dw_gram_kernel(
    const float* __restrict__ w_dw, const float* __restrict__ b_dw)
{
    const int b = blockIdx.z;
    const int h = blockIdx.y;
    const int tile = blockIdx.x;          // 0..127
    const int tr = tile >> 3;             // 16 row-tiles of 8 rows
    const int tc = tile & 7;              // 8 col-tiles of 16 cols
    const int r0 = tr * 8, c0 = tc * 16;

    const int tid = threadIdx.x;
    const int lr = tid >> 4;              // 0..7
    const int lc = tid & 15;              // 0..15
    const int R = r0 + lr, Cc = c0 + lc;
    const int pix = R * WS + Cc;

    __shared__ float halo[10][18];
    __shared__ float qs[128][25];         // [pixel][channel], padded row
    __shared__ float ks[128][25];

    const size_t bq = (size_t)b * C3 * NPIX;

    for (int c = 0; c < CD; c++) {
#pragma unroll
        for (int which = 0; which < 3; which++) {
            const int ch = which * CDIM + h * CD + c;
            __syncthreads();   // previous halo fully consumed
            for (int t = tid; t < 180; t += 128) {
                int hr = t / 18, hc = t % 18;
                int Rg = r0 - 1 + hr, Cg = c0 - 1 + hc;
                float vv = 0.f;
                if (Rg >= 0 && Rg < HS && Cg >= 0 && Cg < WS)
                    vv = g_qkv0[bq + (size_t)ch * NPIX + (size_t)Rg * WS + Cg];
                halo[hr][hc] = vv;
            }
            __syncthreads();
            float wd0 = __ldg(&w_dw[ch * 9 + 0]), wd1 = __ldg(&w_dw[ch * 9 + 1]),
                  wd2 = __ldg(&w_dw[ch * 9 + 2]), wd3 = __ldg(&w_dw[ch * 9 + 3]),
                  wd4 = __ldg(&w_dw[ch * 9 + 4]), wd5 = __ldg(&w_dw[ch * 9 + 5]),
                  wd6 = __ldg(&w_dw[ch * 9 + 6]), wd7 = __ldg(&w_dw[ch * 9 + 7]),
                  wd8 = __ldg(&w_dw[ch * 9 + 8]);
            float s = __ldg(&b_dw[ch]);
            s += halo[lr + 0][lc + 0] * wd0 + halo[lr + 0][lc + 1] * wd1 + halo[lr + 0][lc + 2] * wd2;
            s += halo[lr + 1][lc + 0] * wd3 + halo[lr + 1][lc + 1] * wd4 + halo[lr + 1][lc + 2] * wd5;
            s += halo[lr + 2][lc + 0] * wd6 + halo[lr + 2][lc + 1] * wd7 + halo[lr + 2][lc + 2] * wd8;
            if (which == 0)      qs[tid][c] = s;
            else if (which == 1) ks[tid][c] = s;
            else g_v[(size_t)b * CDIM * NPIX + (size_t)(h * CD + c) * NPIX + pix] = s;
        }
    }
    __syncthreads();

    const int bh = b * HEADS + h;
    // Gram: 96 threads, each owns a 2x3 (c,d) block
    if (tid < 96) {
        const int cb = (tid >> 3) * 2;          // 0,2,..,22
        const int db = (tid & 7) * 3;           // 0,3,..,21
        float a00 = 0, a01 = 0, a02 = 0, a10 = 0, a11 = 0, a12 = 0;
        for (int p = 0; p < 128; p++) {
            float q0 = qs[p][cb], q1 = qs[p][cb + 1];
            float k0 = ks[p][db], k1 = ks[p][db + 1], k2 = ks[p][db + 2];
            a00 += q0 * k0; a01 += q0 * k1; a02 += q0 * k2;
            a10 += q1 * k0; a11 += q1 * k1; a12 += q1 * k2;
        }
        float* Gp = &g_G[(size_t)bh * CD * CD];
        atomicAdd(&Gp[(cb + 0) * CD + db + 0], a00);
        atomicAdd(&Gp[(cb + 0) * CD + db + 1], a01);
        atomicAdd(&Gp[(cb + 0) * CD + db + 2], a02);
        atomicAdd(&Gp[(cb + 1) * CD + db + 0], a10);
        atomicAdd(&Gp[(cb + 1) * CD + db + 1], a11);
        atomicAdd(&Gp[(cb + 1) * CD + db + 2], a12);
    }
    if (tid < 48) {
        const int c = tid % CD;
        float a = 0.f;
        if (tid < CD) {
            for (int p = 0; p < 128; p++) { float q = qs[p][c]; a += q * q; }
            atomicAdd(&g_QN[bh * CD + c], a);
        } else {
            for (int p = 0; p < 128; p++) { float k = ks[p][c]; a += k * k; }
            atomicAdd(&g_KN[bh * CD + c], a);
        }
    }
}

// ---------------- attn + 4x top-k sparse softmax + fold with w_proj ----------------
// grid: BATCH blocks, 256 threads
__global__ __launch_bounds__(256) void attn_fold_kernel(
    const float* __restrict__ wproj, const float* __restrict__ temp,
    const float* __restrict__ a1, const float* __restrict__ a2,
    const float* __restrict__ a3, const float* __restrict__ a4)
{
    const int b = blockIdx.x;
    const int tid = threadIdx.x;
    __shared__ float Wc[HEADS][CD][CD];

    if (tid < HEADS * CD) {
        const int h = tid / CD, c = tid % CD;
        const int bh = b * HEADS + h;
        float attn[CD];
        float qn = fmaxf(sqrtf(g_QN[bh * CD + c]), 1e-12f);
        const float tmp = temp[h];
#pragma unroll
        for (int j = 0; j < CD; j++) {
            float kn = fmaxf(sqrtf(g_KN[bh * CD + j]), 1e-12f);
            attn[j] = g_G[(size_t)bh * CD * CD + c * CD + j] * tmp / (qn * kn);
        }
        float s[CD];
#pragma unroll
        for (int j = 0; j < CD; j++) s[j] = attn[j];
        // insertion sort descending
        for (int i = 1; i < CD; i++) {
            float v = s[i]; int j = i - 1;
            while (j >= 0 && s[j] < v) { s[j + 1] = s[j]; j--; }
            s[j + 1] = v;
        }
        const float thr0 = s[11], thr1 = s[15], thr2 = s[17], thr3 = s[18];
        const float m = s[0];
        float e[CD];
        float sum0 = 0, sum1 = 0, sum2 = 0, sum3 = 0;
#pragma unroll
        for (int j = 0; j < CD; j++) {
            e[j] = expf(attn[j] - m);
            if (attn[j] >= thr0) sum0 += e[j];
            if (attn[j] >= thr1) sum1 += e[j];
            if (attn[j] >= thr2) sum2 += e[j];
            if (attn[j] >= thr3) sum3 += e[j];
        }
        const float A1 = a1[0], A2 = a2[0], A3 = a3[0], A4 = a4[0];
        const float r0 = A1 / sum0, r1 = A2 / sum1, r2 = A3 / sum2, r3 = A4 / sum3;
#pragma unroll
        for (int j = 0; j < CD; j++) {
            float w = 0.f;
            if (attn[j] >= thr0) w += r0 * e[j];
            if (attn[j] >= thr1) w += r1 * e[j];
            if (attn[j] >= thr2) w += r2 * e[j];
            if (attn[j] >= thr3) w += r3 * e[j];
            Wc[h][c][j] = w;
        }
    }
    __syncthreads();

    // M[b][o][h*24+d] = sum_c wproj[o][h*24+c] * Wc[h][c][d]
    for (int idx = tid; idx < CDIM * CDIM; idx += blockDim.x) {
        const int o = idx / CDIM;
        const int jc = idx % CDIM;
        const int hh = jc / CD, d = jc % CD;
        float acc = 0.f;
#pragma unroll
        for (int c = 0; c < CD; c++)
            acc += __ldg(&wproj[o * CDIM + hh * CD + c]) * Wc[hh][c][d];
        g_M[(size_t)b * CDIM * CDIM + idx] = acc;
    }
}

// ---------------- launch ----------------
extern "C" void kernel_launch(void* const* d_in, const int* in_sizes, int n_in,
                              void* d_out, int out_size)
{
    const float* x      = (const float*)d_in[0];
    const float* w_qkv  = (const float*)d_in[1];
    const float* b_qkv  = (const float*)d_in[2];
    const float* w_dw   = (const float*)d_in[3];
    const float* b_dw   = (const float*)d_in[4];
    const float* w_proj = (const float*)d_in[5];
    const float* b_proj = (const float*)d_in[6];
    const float* temp   = (const float*)d_in[7];
    const float* a1     = (const float*)d_in[8];
    const float* a2     = (const float*)d_in[9];
    const float* a3     = (const float*)d_in[10];
    const float* a4     = (const float*)d_in[11];
    float* out = (float*)d_out;

    init_stats_kernel<<<1, 256>>>();

    // qkv 1x1 conv: 576 x 16384 per batch
    gemm_kernel<0><<<dim3(NPIX / 128, C3 / 64, BATCH), 128>>>(w_qkv, x, b_qkv, nullptr);

    // dw conv + gram
    dw_gram_kernel<<<dim3(128, HEADS, BATCH), 128>>>(w_dw, b_dw);

    // attention + fold
    attn_fold_kernel<<<BATCH, 256>>>(w_proj, temp, a1, a2, a3, a4);

    // final: out[b] = M[b] @ v[b] + b_proj
    gemm_kernel<1><<<dim3(NPIX / 128, CDIM / 64, BATCH), 128>>>(nullptr, nullptr, b_proj, out);
}

// round 6
// speedup vs baseline: 1.0389x; 1.0389x over previous
#include <cuda_runtime.h>
#include <cstdint>

#define HS 128
#define WS 128
#define NPIX 16384
#define BATCH 8
#define CDIM 192
#define C3 576
#define HEADS 8
#define CD 24

// ---------------- scratch (device globals; no allocation allowed) ----------------
__device__ __align__(128) float g_qkv0[(size_t)BATCH * C3 * NPIX];   // after 1x1 conv
__device__ __align__(128) float g_v[(size_t)BATCH * CDIM * NPIX];    // v after dw conv
__device__ __align__(128) float g_G[BATCH * HEADS * CD * CD];
__device__ __align__(128) float g_QN[BATCH * HEADS * CD];
__device__ __align__(128) float g_KN[BATCH * HEADS * CD];
__device__ __align__(128) float g_W[BATCH * HEADS * CD * CD];
__device__ __align__(128) float g_M[BATCH * CDIM * CDIM];

// ---------------- init ----------------
__global__ void init_stats_kernel() {
    int tot = BATCH * HEADS * CD * CD;
    for (int i = threadIdx.x; i < tot; i += blockDim.x) g_G[i] = 0.f;
    int tot2 = BATCH * HEADS * CD;
    for (int i = threadIdx.x; i < tot2; i += blockDim.x) { g_QN[i] = 0.f; g_KN[i] = 0.f; }
}

// ---------------- SGEMM (R1-verbatim, known clean): C[b] = A @ B[b] + bias ----------------
// MODE 0: A = w_qkv (576x192), B = x[b] (192xN), C = g_qkv0[b]
// MODE 1: A = g_M[b] (192x192), B = g_v[b] (192xN), C = out[b]
// BM=64, BN=128, BK=8, TM=TN=8, 128 threads
template<int MODE>
__global__ __launch_bounds__(128) void gemm_kernel(
    const float* __restrict__ Aext, const float* __restrict__ Bext,
    const float* __restrict__ bias, float* __restrict__ Cext)
{
    constexpr int K = CDIM;
    const int b = blockIdx.z;
    const float* Ab = (MODE == 0) ? Aext : (g_M + (size_t)b * CDIM * CDIM);
    const float* Bb = (MODE == 0) ? (Bext + (size_t)b * CDIM * NPIX)
                                  : (g_v + (size_t)b * CDIM * NPIX);
    float* Cb = (MODE == 0) ? (g_qkv0 + (size_t)b * C3 * NPIX)
                            : (Cext + (size_t)b * CDIM * NPIX);

    const int n0 = blockIdx.x * 128;
    const int m0 = blockIdx.y * 64;

    __shared__ __align__(16) float As[8][64];
    __shared__ __align__(16) float Bs[8][128];

    const int tid = threadIdx.x;
    const int tx = tid & 15;        // 0..15 -> n groups of 8
    const int ty = tid >> 4;        // 0..7  -> m groups of 8

    const int arow = tid >> 1;            // 0..63
    const int acol4 = (tid & 1) * 4;      // 0 or 4
    const int bk = tid >> 5;              // 0..3
    const int bn4 = (tid & 31) * 4;       // 0..124

    float acc[8][8];
#pragma unroll
    for (int i = 0; i < 8; i++)
#pragma unroll
        for (int j = 0; j < 8; j++) acc[i][j] = 0.f;

    for (int k0 = 0; k0 < K; k0 += 8) {
        float4 av = *(const float4*)&Ab[(size_t)(m0 + arow) * K + k0 + acol4];
        As[acol4 + 0][arow] = av.x;
        As[acol4 + 1][arow] = av.y;
        As[acol4 + 2][arow] = av.z;
        As[acol4 + 3][arow] = av.w;
        float4 bv0 = *(const float4*)&Bb[(size_t)(k0 + bk) * NPIX + n0 + bn4];
        float4 bv1 = *(const float4*)&Bb[(size_t)(k0 + bk + 4) * NPIX + n0 + bn4];
        *(float4*)&Bs[bk][bn4] = bv0;
        *(float4*)&Bs[bk + 4][bn4] = bv1;
        __syncthreads();
#pragma unroll
        for (int kk = 0; kk < 8; kk++) {
            float ra[8], rb[8];
            *(float4*)&ra[0] = *(const float4*)&As[kk][ty * 8];
            *(float4*)&ra[4] = *(const float4*)&As[kk][ty * 8 + 4];
            *(float4*)&rb[0] = *(const float4*)&Bs[kk][tx * 8];
            *(float4*)&rb[4] = *(const float4*)&Bs[kk][tx * 8 + 4];
#pragma unroll
            for (int i = 0; i < 8; i++)
#pragma unroll
                for (int j = 0; j < 8; j++) acc[i][j] += ra[i] * rb[j];
        }
        __syncthreads();
    }

#pragma unroll
    for (int i = 0; i < 8; i++) {
        int o = m0 + ty * 8 + i;
        float bo = bias[o];
        size_t base = (size_t)o * NPIX + n0 + tx * 8;
        float4 v0 = make_float4(acc[i][0] + bo, acc[i][1] + bo, acc[i][2] + bo, acc[i][3] + bo);
        float4 v1 = make_float4(acc[i][4] + bo, acc[i][5] + bo, acc[i][6] + bo, acc[i][7] + bo);
        *(float4*)&Cb[base] = v0;
        *(float4*)&Cb[base + 4] = v1;
    }
}

// ---------------- dw conv (3x3) + Gram/norm reduction + v write ----------------
// grid: (64 tiles of 16x16, HEADS, BATCH), 256 threads, dynamic smem
#define DW_QS 0
#define DW_KS 6400
#define DW_HQ 12800
#define DW_HK 13152
#define DW_HV 13504
#define DW_SMEM_FLOATS 13856

__global__ __launch_bounds__(256) void dw_gram_kernel(
    const float* __restrict__ w_dw, const float* __restrict__ b_dw)
{
    extern __shared__ float ds[];
    float* qs = ds + DW_QS;
    float* ks2 = ds + DW_KS;
    float* hQ = ds + DW_HQ;
    float* hK = ds + DW_HK;
    float* hV = ds + DW_HV;

    const int b = blockIdx.z, h = blockIdx.y, tile = blockIdx.x;
    const int r0 = (tile >> 3) * 16, c0 = (tile & 7) * 16;
    const int tid = threadIdx.x;
    const int lr = tid >> 4, lc = tid & 15;
    const int R = r0 + lr, Cc = c0 + lc;
    const int pix = R * WS + Cc;
    const size_t bq = (size_t)b * C3 * NPIX;

    for (int c = 0; c < CD; c++) {
        __syncthreads();
        for (int t = tid; t < 3 * 324; t += 256) {
            int which = t / 324, e = t % 324;
            int hr = e / 18, hc = e % 18;
            int Rg = r0 - 1 + hr, Cg = c0 - 1 + hc;
            float vv = 0.f;
            int ch = which * CDIM + h * CD + c;
            if (Rg >= 0 && Rg < HS && Cg >= 0 && Cg < WS)
                vv = g_qkv0[bq + (size_t)ch * NPIX + (size_t)Rg * WS + Cg];
            float* dst = (which == 0) ? hQ : (which == 1) ? hK : hV;
            dst[hr * 19 + hc] = vv;
        }
        __syncthreads();
#pragma unroll
        for (int which = 0; which < 3; which++) {
            const int ch = which * CDIM + h * CD + c;
            const float* halo = (which == 0) ? hQ : (which == 1) ? hK : hV;
            float s = __ldg(&b_dw[ch]);
            const float* wp = w_dw + ch * 9;
            s += halo[(lr + 0) * 19 + lc + 0] * __ldg(&wp[0]) + halo[(lr + 0) * 19 + lc + 1] * __ldg(&wp[1]) + halo[(lr + 0) * 19 + lc + 2] * __ldg(&wp[2]);
            s += halo[(lr + 1) * 19 + lc + 0] * __ldg(&wp[3]) + halo[(lr + 1) * 19 + lc + 1] * __ldg(&wp[4]) + halo[(lr + 1) * 19 + lc + 2] * __ldg(&wp[5]);
            s += halo[(lr + 2) * 19 + lc + 0] * __ldg(&wp[6]) + halo[(lr + 2) * 19 + lc + 1] * __ldg(&wp[7]) + halo[(lr + 2) * 19 + lc + 2] * __ldg(&wp[8]);
            if (which == 0) qs[tid * 25 + c] = s;
            else if (which == 1) ks2[tid * 25 + c] = s;
            else g_v[(size_t)b * CDIM * NPIX + (size_t)(h * CD + c) * NPIX + pix] = s;
        }
    }
    __syncthreads();

    const int bh = b * HEADS + h;
    if (tid < 192) {
        const int cc = tid >> 3;
        const int db = (tid & 7) * 3;
        float a0 = 0.f, a1 = 0.f, a2 = 0.f;
        for (int p = 0; p < 256; p++) {
            float qv = qs[p * 25 + cc];
            a0 += qv * ks2[p * 25 + db];
            a1 += qv * ks2[p * 25 + db + 1];
            a2 += qv * ks2[p * 25 + db + 2];
        }
        float* Gp = g_G + (size_t)bh * CD * CD + cc * CD + db;
        atomicAdd(&Gp[0], a0);
        atomicAdd(&Gp[1], a1);
        atomicAdd(&Gp[2], a2);
    } else if (tid < 216) {
        const int c = tid - 192;
        float a = 0.f;
        for (int p = 0; p < 256; p++) { float qv = qs[p * 25 + c]; a += qv * qv; }
        atomicAdd(&g_QN[bh * CD + c], a);
    } else if (tid < 240) {
        const int c = tid - 216;
        float a = 0.f;
        for (int p = 0; p < 256; p++) { float kv = ks2[p * 25 + c]; a += kv * kv; }
        atomicAdd(&g_KN[bh * CD + c], a);
    }
}

// ---------------- attn: norms + 4x top-k sparse softmax via rank selection -> g_W ----------------
__global__ __launch_bounds__(32) void attn_kernel(
    const float* __restrict__ temp,
    const float* __restrict__ a1, const float* __restrict__ a2,
    const float* __restrict__ a3, const float* __restrict__ a4)
{
    const int bh = blockIdx.x;
    const int h = bh % HEADS;
    const int c = threadIdx.x;
    if (c >= CD) return;
    float attn[CD];
    float qn = fmaxf(sqrtf(g_QN[bh * CD + c]), 1e-12f);
    const float tmp = temp[h];
#pragma unroll
    for (int j = 0; j < CD; j++) {
        float kn = fmaxf(sqrtf(g_KN[bh * CD + j]), 1e-12f);
        attn[j] = g_G[(size_t)bh * CD * CD + c * CD + j] * tmp / (qn * kn);
    }
    float m = attn[0];
#pragma unroll
    for (int j = 1; j < CD; j++) m = fmaxf(m, attn[j]);
    // rank[j] = #{i : attn[i] > attn[j] || (attn[i]==attn[j] && i<j)}  (lax.top_k stable tie order)
    int rank[CD];
#pragma unroll
    for (int j = 0; j < CD; j++) {
        int r = 0;
#pragma unroll
        for (int i = 0; i < CD; i++) {
            bool gt = (attn[i] > attn[j]) || (attn[i] == attn[j] && i < j);
            r += gt ? 1 : 0;
        }
        rank[j] = r;
    }
    float e[CD];
    float sum0 = 0.f, sum1 = 0.f, sum2 = 0.f, sum3 = 0.f;
#pragma unroll
    for (int j = 0; j < CD; j++) {
        e[j] = expf(attn[j] - m);
        if (rank[j] < 12) sum0 += e[j];
        if (rank[j] < 16) sum1 += e[j];
        if (rank[j] < 18) sum2 += e[j];
        if (rank[j] < 19) sum3 += e[j];
    }
    const float r0 = a1[0] / sum0, r1 = a2[0] / sum1, r2 = a3[0] / sum2, r3 = a4[0] / sum3;
    float* Wp = g_W + (size_t)bh * CD * CD + c * CD;
#pragma unroll
    for (int j = 0; j < CD; j++) {
        float w = 0.f;
        if (rank[j] < 12) w += r0 * e[j];
        if (rank[j] < 16) w += r1 * e[j];
        if (rank[j] < 18) w += r2 * e[j];
        if (rank[j] < 19) w += r3 * e[j];
        Wp[j] = w;
    }
}

// ---------------- fold: M[b][o][h*24+d] = sum_c wproj[o][h*24+c] * W[b,h][c][d] ----------------
__global__ __launch_bounds__(256) void fold_kernel(const float* __restrict__ wproj)
{
    const int b = blockIdx.x, s = blockIdx.y;
    const int t = threadIdx.x;
    const int o = s * 32 + (t >> 3);
    const int hh = t & 7;
    const float* Wp = g_W + ((size_t)(b * HEADS + hh)) * CD * CD;
    float acc[CD];
#pragma unroll
    for (int d = 0; d < CD; d++) acc[d] = 0.f;
#pragma unroll
    for (int c = 0; c < CD; c++) {
        float w = __ldg(&wproj[o * CDIM + hh * CD + c]);
#pragma unroll
        for (int d = 0; d < CD; d++) acc[d] += w * __ldg(&Wp[c * CD + d]);
    }
    float* Mo = g_M + (size_t)b * CDIM * CDIM + (size_t)o * CDIM + hh * CD;
#pragma unroll
    for (int d = 0; d < CD; d++) Mo[d] = acc[d];
}

// ---------------- launch ----------------
extern "C" void kernel_launch(void* const* d_in, const int* in_sizes, int n_in,
                              void* d_out, int out_size)
{
    const float* x      = (const float*)d_in[0];
    const float* w_qkv  = (const float*)d_in[1];
    const float* b_qkv  = (const float*)d_in[2];
    const float* w_dw   = (const float*)d_in[3];
    const float* b_dw   = (const float*)d_in[4];
    const float* w_proj = (const float*)d_in[5];
    const float* b_proj = (const float*)d_in[6];
    const float* temp   = (const float*)d_in[7];
    const float* a1     = (const float*)d_in[8];
    const float* a2     = (const float*)d_in[9];
    const float* a3     = (const float*)d_in[10];
    const float* a4     = (const float*)d_in[11];
    float* out = (float*)d_out;

    cudaFuncSetAttribute(dw_gram_kernel, cudaFuncAttributeMaxDynamicSharedMemorySize, DW_SMEM_FLOATS * 4);

    init_stats_kernel<<<1, 256>>>();

    // qkv 1x1 conv: g_qkv0[b] = w_qkv @ x[b] + b_qkv   (576/64 = 9 m-tiles)
    gemm_kernel<0><<<dim3(NPIX / 128, C3 / 64, BATCH), 128>>>(w_qkv, x, b_qkv, nullptr);

    // dw conv + gram
    dw_gram_kernel<<<dim3(64, HEADS, BATCH), 256, DW_SMEM_FLOATS * 4>>>(w_dw, b_dw);

    // attention weights + fold
    attn_kernel<<<BATCH * HEADS, 32>>>(temp, a1, a2, a3, a4);
    fold_kernel<<<dim3(BATCH, 6), 256>>>(w_proj);

    // out[b] = g_M[b] @ g_v[b] + b_proj   (192/64 = 3 m-tiles)
    gemm_kernel<1><<<dim3(NPIX / 128, CDIM / 64, BATCH), 128>>>(nullptr, nullptr, b_proj, out);
}

// round 8
// speedup vs baseline: 1.0429x; 1.0038x over previous
#include <cuda_runtime.h>
#include <cstdint>

#define HS 128
#define WS 128
#define NPIX 16384
#define BATCH 8
#define CDIM 192
#define C3 576
#define HEADS 8
#define CD 24

// ---------------- scratch (device globals; no allocation allowed) ----------------
__device__ __align__(128) float g_qkv0[(size_t)BATCH * C3 * NPIX];   // after 1x1 conv
__device__ __align__(128) float g_v[(size_t)BATCH * CDIM * NPIX];    // v after dw conv
__device__ __align__(128) float g_G[BATCH * HEADS * CD * CD];
__device__ __align__(128) float g_QN[BATCH * HEADS * CD];
__device__ __align__(128) float g_KN[BATCH * HEADS * CD];
__device__ __align__(128) float g_W[BATCH * HEADS * CD * CD];
__device__ __align__(128) float g_M[BATCH * CDIM * CDIM];

// ---------------- packed f32x2 helpers (Blackwell FFMA2) ----------------
#define PACK2(D, X, Y) asm("mov.b64 %0, {%1, %2};" : "=l"(D) : "f"(X), "f"(Y))
#define DUP2(D, X)     asm("mov.b64 %0, {%1, %1};" : "=l"(D) : "f"(X))
#define UNPK2(X, Y, S) asm("mov.b64 {%0, %1}, %2;" : "=f"(X), "=f"(Y) : "l"(S))
#define FMA2(ACC, A, B) asm("fma.rn.f32x2 %0, %1, %2, %0;" : "+l"(ACC) : "l"(A), "l"(B))

// ---------------- init ----------------
__global__ void init_stats_kernel() {
    int tot = BATCH * HEADS * CD * CD;
    for (int i = threadIdx.x; i < tot; i += blockDim.x) g_G[i] = 0.f;
    int tot2 = BATCH * HEADS * CD;
    for (int i = threadIdx.x; i < tot2; i += blockDim.x) { g_QN[i] = 0.f; g_KN[i] = 0.f; }
}

// ---------------- SGEMM with packed f32x2 FMA: C[b] = A @ B[b] + bias ----------------
// MODE 0: A = w_qkv (576x192), B = x[b] (192xN), C = g_qkv0[b]
// MODE 1: A = g_M[b] (192x192), B = g_v[b] (192xN), C = out[b]
// BM=64, BN=128, BK=8, TM=TN=8, 128 threads (R6 structure; inner math -> FFMA2)
template<int MODE>
__global__ __launch_bounds__(128) void gemm_kernel(
    const float* __restrict__ Aext, const float* __restrict__ Bext,
    const float* __restrict__ bias, float* __restrict__ Cext)
{
    constexpr int K = CDIM;
    const int b = blockIdx.z;
    const float* Ab = (MODE == 0) ? Aext : (g_M + (size_t)b * CDIM * CDIM);
    const float* Bb = (MODE == 0) ? (Bext + (size_t)b * CDIM * NPIX)
                                  : (g_v + (size_t)b * CDIM * NPIX);
    float* Cb = (MODE == 0) ? (g_qkv0 + (size_t)b * C3 * NPIX)
                            : (Cext + (size_t)b * CDIM * NPIX);

    const int n0 = blockIdx.x * 128;
    const int m0 = blockIdx.y * 64;

    __shared__ __align__(16) float As[8][64];
    __shared__ __align__(16) float Bs[8][128];

    const int tid = threadIdx.x;
    const int tx = tid & 15;        // 0..15 -> n groups of 8
    const int ty = tid >> 4;        // 0..7  -> m groups of 8

    const int arow = tid >> 1;            // 0..63
    const int acol4 = (tid & 1) * 4;      // 0 or 4
    const int bk = tid >> 5;              // 0..3
    const int bn4 = (tid & 31) * 4;       // 0..124

    // acc2[i][j] = packed {C[i][2j], C[i][2j+1]}
    unsigned long long acc2[8][4];
#pragma unroll
    for (int i = 0; i < 8; i++)
#pragma unroll
        for (int j = 0; j < 4; j++) acc2[i][j] = 0ull;

    for (int k0 = 0; k0 < K; k0 += 8) {
        float4 av = *(const float4*)&Ab[(size_t)(m0 + arow) * K + k0 + acol4];
        As[acol4 + 0][arow] = av.x;
        As[acol4 + 1][arow] = av.y;
        As[acol4 + 2][arow] = av.z;
        As[acol4 + 3][arow] = av.w;
        float4 bv0 = *(const float4*)&Bb[(size_t)(k0 + bk) * NPIX + n0 + bn4];
        float4 bv1 = *(const float4*)&Bb[(size_t)(k0 + bk + 4) * NPIX + n0 + bn4];
        *(float4*)&Bs[bk][bn4] = bv0;
        *(float4*)&Bs[bk + 4][bn4] = bv1;
        __syncthreads();
#pragma unroll
        for (int kk = 0; kk < 8; kk++) {
            float4 ra0 = *(const float4*)&As[kk][ty * 8];
            float4 ra1 = *(const float4*)&As[kk][ty * 8 + 4];
            float4 rb0 = *(const float4*)&Bs[kk][tx * 8];
            float4 rb1 = *(const float4*)&Bs[kk][tx * 8 + 4];
            unsigned long long bp0, bp1, bp2, bp3;
            PACK2(bp0, rb0.x, rb0.y);
            PACK2(bp1, rb0.z, rb0.w);
            PACK2(bp2, rb1.x, rb1.y);
            PACK2(bp3, rb1.z, rb1.w);
            unsigned long long a2[8];
            DUP2(a2[0], ra0.x); DUP2(a2[1], ra0.y); DUP2(a2[2], ra0.z); DUP2(a2[3], ra0.w);
            DUP2(a2[4], ra1.x); DUP2(a2[5], ra1.y); DUP2(a2[6], ra1.z); DUP2(a2[7], ra1.w);
#pragma unroll
            for (int i = 0; i < 8; i++) {
                FMA2(acc2[i][0], a2[i], bp0);
                FMA2(acc2[i][1], a2[i], bp1);
                FMA2(acc2[i][2], a2[i], bp2);
                FMA2(acc2[i][3], a2[i], bp3);
            }
        }
        __syncthreads();
    }

#pragma unroll
    for (int i = 0; i < 8; i++) {
        int o = m0 + ty * 8 + i;
        float bo = bias[o];
        size_t base = (size_t)o * NPIX + n0 + tx * 8;
        float c0, c1, c2, c3, c4, c5, c6, c7;
        UNPK2(c0, c1, acc2[i][0]);
        UNPK2(c2, c3, acc2[i][1]);
        UNPK2(c4, c5, acc2[i][2]);
        UNPK2(c6, c7, acc2[i][3]);
        float4 v0 = make_float4(c0 + bo, c1 + bo, c2 + bo, c3 + bo);
        float4 v1 = make_float4(c4 + bo, c5 + bo, c6 + bo, c7 + bo);
        *(float4*)&Cb[base] = v0;
        *(float4*)&Cb[base + 4] = v1;
    }
}

// ---------------- dw conv (3x3) + Gram/norm reduction + v write ----------------
// grid: (64 tiles of 16x16, HEADS, BATCH), 256 threads, dynamic smem
#define DW_QS 0
#define DW_KS 6400
#define DW_HQ 12800
#define DW_HK 13152
#define DW_HV 13504
#define DW_SMEM_FLOATS 13856

__global__ __launch_bounds__(256) void dw_gram_kernel(
    const float* __restrict__ w_dw, const float* __restrict__ b_dw)
{
    extern __shared__ float ds[];
    float* qs = ds + DW_QS;
    float* ks2 = ds + DW_KS;
    float* hQ = ds + DW_HQ;
    float* hK = ds + DW_HK;
    float* hV = ds + DW_HV;

    const int b = blockIdx.z, h = blockIdx.y, tile = blockIdx.x;
    const int r0 = (tile >> 3) * 16, c0 = (tile & 7) * 16;
    const int tid = threadIdx.x;
    const int lr = tid >> 4, lc = tid & 15;
    const int R = r0 + lr, Cc = c0 + lc;
    const int pix = R * WS + Cc;
    const size_t bq = (size_t)b * C3 * NPIX;

    for (int c = 0; c < CD; c++) {
        __syncthreads();
        for (int t = tid; t < 3 * 324; t += 256) {
            int which = t / 324, e = t % 324;
            int hr = e / 18, hc = e % 18;
            int Rg = r0 - 1 + hr, Cg = c0 - 1 + hc;
            float vv = 0.f;
            int ch = which * CDIM + h * CD + c;
            if (Rg >= 0 && Rg < HS && Cg >= 0 && Cg < WS)
                vv = g_qkv0[bq + (size_t)ch * NPIX + (size_t)Rg * WS + Cg];
            float* dst = (which == 0) ? hQ : (which == 1) ? hK : hV;
            dst[hr * 19 + hc] = vv;
        }
        __syncthreads();
#pragma unroll
        for (int which = 0; which < 3; which++) {
            const int ch = which * CDIM + h * CD + c;
            const float* halo = (which == 0) ? hQ : (which == 1) ? hK : hV;
            float s = __ldg(&b_dw[ch]);
            const float* wp = w_dw + ch * 9;
            s += halo[(lr + 0) * 19 + lc + 0] * __ldg(&wp[0]) + halo[(lr + 0) * 19 + lc + 1] * __ldg(&wp[1]) + halo[(lr + 0) * 19 + lc + 2] * __ldg(&wp[2]);
            s += halo[(lr + 1) * 19 + lc + 0] * __ldg(&wp[3]) + halo[(lr + 1) * 19 + lc + 1] * __ldg(&wp[4]) + halo[(lr + 1) * 19 + lc + 2] * __ldg(&wp[5]);
            s += halo[(lr + 2) * 19 + lc + 0] * __ldg(&wp[6]) + halo[(lr + 2) * 19 + lc + 1] * __ldg(&wp[7]) + halo[(lr + 2) * 19 + lc + 2] * __ldg(&wp[8]);
            if (which == 0) qs[tid * 25 + c] = s;
            else if (which == 1) ks2[tid * 25 + c] = s;
            else g_v[(size_t)b * CDIM * NPIX + (size_t)(h * CD + c) * NPIX + pix] = s;
        }
    }
    __syncthreads();

    const int bh = b * HEADS + h;
    if (tid < 192) {
        const int cc = tid >> 3;
        const int db = (tid & 7) * 3;
        float a0 = 0.f, a1 = 0.f, a2 = 0.f;
        for (int p = 0; p < 256; p++) {
            float qv = qs[p * 25 + cc];
            a0 += qv * ks2[p * 25 + db];
            a1 += qv * ks2[p * 25 + db + 1];
            a2 += qv * ks2[p * 25 + db + 2];
        }
        float* Gp = g_G + (size_t)bh * CD * CD + cc * CD + db;
        atomicAdd(&Gp[0], a0);
        atomicAdd(&Gp[1], a1);
        atomicAdd(&Gp[2], a2);
    } else if (tid < 216) {
        const int c = tid - 192;
        float a = 0.f;
        for (int p = 0; p < 256; p++) { float qv = qs[p * 25 + c]; a += qv * qv; }
        atomicAdd(&g_QN[bh * CD + c], a);
    } else if (tid < 240) {
        const int c = tid - 216;
        float a = 0.f;
        for (int p = 0; p < 256; p++) { float kv = ks2[p * 25 + c]; a += kv * kv; }
        atomicAdd(&g_KN[bh * CD + c], a);
    }
}

// ---------------- attn: norms + 4x top-k sparse softmax via rank selection -> g_W ----------------
__global__ __launch_bounds__(32) void attn_kernel(
    const float* __restrict__ temp,
    const float* __restrict__ a1, const float* __restrict__ a2,
    const float* __restrict__ a3, const float* __restrict__ a4)
{
    const int bh = blockIdx.x;
    const int h = bh % HEADS;
    const int c = threadIdx.x;
    if (c >= CD) return;
    float attn[CD];
    float qn = fmaxf(sqrtf(g_QN[bh * CD + c]), 1e-12f);
    const float tmp = temp[h];
#pragma unroll
    for (int j = 0; j < CD; j++) {
        float kn = fmaxf(sqrtf(g_KN[bh * CD + j]), 1e-12f);
        attn[j] = g_G[(size_t)bh * CD * CD + c * CD + j] * tmp / (qn * kn);
    }
    float m = attn[0];
#pragma unroll
    for (int j = 1; j < CD; j++) m = fmaxf(m, attn[j]);
    // rank[j] = #{i : attn[i] > attn[j] || (attn[i]==attn[j] && i<j)}  (lax.top_k stable tie order)
    int rank[CD];
#pragma unroll
    for (int j = 0; j < CD; j++) {
        int r = 0;
#pragma unroll
        for (int i = 0; i < CD; i++) {
            bool gt = (attn[i] > attn[j]) || (attn[i] == attn[j] && i < j);
            r += gt ? 1 : 0;
        }
        rank[j] = r;
    }
    float e[CD];
    float sum0 = 0.f, sum1 = 0.f, sum2 = 0.f, sum3 = 0.f;
#pragma unroll
    for (int j = 0; j < CD; j++) {
        e[j] = expf(attn[j] - m);
        if (rank[j] < 12) sum0 += e[j];
        if (rank[j] < 16) sum1 += e[j];
        if (rank[j] < 18) sum2 += e[j];
        if (rank[j] < 19) sum3 += e[j];
    }
    const float r0 = a1[0] / sum0, r1 = a2[0] / sum1, r2 = a3[0] / sum2, r3 = a4[0] / sum3;
    float* Wp = g_W + (size_t)bh * CD * CD + c * CD;
#pragma unroll
    for (int j = 0; j < CD; j++) {
        float w = 0.f;
        if (rank[j] < 12) w += r0 * e[j];
        if (rank[j] < 16) w += r1 * e[j];
        if (rank[j] < 18) w += r2 * e[j];
        if (rank[j] < 19) w += r3 * e[j];
        Wp[j] = w;
    }
}

// ---------------- fold: M[b][o][h*24+d] = sum_c wproj[o][h*24+c] * W[b,h][c][d] ----------------
__global__ __launch_bounds__(256) void fold_kernel(const float* __restrict__ wproj)
{
    const int b = blockIdx.x, s = blockIdx.y;
    const int t = threadIdx.x;
    const int o = s * 32 + (t >> 3);
    const int hh = t & 7;
    const float* Wp = g_W + ((size_t)(b * HEADS + hh)) * CD * CD;
    float acc[CD];
#pragma unroll
    for (int d = 0; d < CD; d++) acc[d] = 0.f;
#pragma unroll
    for (int c = 0; c < CD; c++) {
        float w = __ldg(&wproj[o * CDIM + hh * CD + c]);
#pragma unroll
        for (int d = 0; d < CD; d++) acc[d] += w * __ldg(&Wp[c * CD + d]);
    }
    float* Mo = g_M + (size_t)b * CDIM * CDIM + (size_t)o * CDIM + hh * CD;
#pragma unroll
    for (int d = 0; d < CD; d++) Mo[d] = acc[d];
}

// ---------------- launch ----------------
extern "C" void kernel_launch(void* const* d_in, const int* in_sizes, int n_in,
                              void* d_out, int out_size)
{
    const float* x      = (const float*)d_in[0];
    const float* w_qkv  = (const float*)d_in[1];
    const float* b_qkv  = (const float*)d_in[2];
    const float* w_dw   = (const float*)d_in[3];
    const float* b_dw   = (const float*)d_in[4];
    const float* w_proj = (const float*)d_in[5];
    const float* b_proj = (const float*)d_in[6];
    const float* temp   = (const float*)d_in[7];
    const float* a1     = (const float*)d_in[8];
    const float* a2     = (const float*)d_in[9];
    const float* a3     = (const float*)d_in[10];
    const float* a4     = (const float*)d_in[11];
    float* out = (float*)d_out;

    cudaFuncSetAttribute(dw_gram_kernel, cudaFuncAttributeMaxDynamicSharedMemorySize, DW_SMEM_FLOATS * 4);

    init_stats_kernel<<<1, 256>>>();

    // qkv 1x1 conv: g_qkv0[b] = w_qkv @ x[b] + b_qkv   (576/64 = 9 m-tiles)
    gemm_kernel<0><<<dim3(NPIX / 128, C3 / 64, BATCH), 128>>>(w_qkv, x, b_qkv, nullptr);

    // dw conv + gram
    dw_gram_kernel<<<dim3(64, HEADS, BATCH), 256, DW_SMEM_FLOATS * 4>>>(w_dw, b_dw);

    // attention weights + fold
    attn_kernel<<<BATCH * HEADS, 32>>>(temp, a1, a2, a3, a4);
    fold_kernel<<<dim3(BATCH, 6), 256>>>(w_proj);

    // out[b] = g_M[b] @ g_v[b] + b_proj   (192/64 = 3 m-tiles)
    gemm_kernel<1><<<dim3(NPIX / 128, CDIM / 64, BATCH), 128>>>(nullptr, nullptr, b_proj, out);
}

// round 10
// speedup vs baseline: 1.1483x; 1.1011x over previous
#include <cuda_runtime.h>
#include <cstdint>

#define HS 128
#define WS 128
#define NPIX 16384
#define BATCH 8
#define CDIM 192
#define C3 576
#define HEADS 8
#define CD 24

// ---------------- scratch (device globals; no allocation allowed) ----------------
__device__ __align__(128) float g_qkv0[(size_t)BATCH * C3 * NPIX];   // after 1x1 conv
__device__ __align__(128) float g_v[(size_t)BATCH * CDIM * NPIX];    // v after dw conv
__device__ __align__(128) float g_G[BATCH * HEADS * CD * CD];
__device__ __align__(128) float g_QN[BATCH * HEADS * CD];
__device__ __align__(128) float g_KN[BATCH * HEADS * CD];
__device__ __align__(128) float g_W[BATCH * HEADS * CD * CD];
__device__ __align__(128) float g_M[BATCH * CDIM * CDIM];

// ---------------- init ----------------
__global__ void init_stats_kernel() {
    int tot = BATCH * HEADS * CD * CD;
    for (int i = threadIdx.x; i < tot; i += blockDim.x) g_G[i] = 0.f;
    int tot2 = BATCH * HEADS * CD;
    for (int i = threadIdx.x; i < tot2; i += blockDim.x) { g_QN[i] = 0.f; g_KN[i] = 0.f; }
}

// ---------------- SGEMM: C[b] = A @ B[b] + bias ----------------
// MODE 0: A = w_qkv (576x192), B = x[b] (192xN), C = g_qkv0[b]
// MODE 1: A = g_M[b] (192x192), B = g_v[b] (192xN), C = out[b]
// BM=64, BN=128, BK=16, TM=TN=8, 128 threads
template<int MODE>
__global__ __launch_bounds__(128) void gemm_kernel(
    const float* __restrict__ Aext, const float* __restrict__ Bext,
    const float* __restrict__ bias, float* __restrict__ Cext)
{
    constexpr int K = CDIM;
    const int b = blockIdx.z;
    const float* Ab = (MODE == 0) ? Aext : (g_M + (size_t)b * CDIM * CDIM);
    const float* Bb = (MODE == 0) ? (Bext + (size_t)b * CDIM * NPIX)
                                  : (g_v + (size_t)b * CDIM * NPIX);
    float* Cb = (MODE == 0) ? (g_qkv0 + (size_t)b * C3 * NPIX)
                            : (Cext + (size_t)b * CDIM * NPIX);

    const int n0 = blockIdx.x * 128;
    const int m0 = blockIdx.y * 64;

    __shared__ __align__(16) float As[16][64];
    __shared__ __align__(16) float Bs[16][128];

    const int tid = threadIdx.x;
    const int tx = tid & 15;        // 0..15 -> n groups of 8
    const int ty = tid >> 4;        // 0..7  -> m groups of 8

    const int arow = tid >> 1;            // 0..63
    const int acol = (tid & 1) * 8;       // 0 or 8

    float acc[8][8];
#pragma unroll
    for (int i = 0; i < 8; i++)
#pragma unroll
        for (int j = 0; j < 8; j++) acc[i][j] = 0.f;

    for (int k0 = 0; k0 < K; k0 += 16) {
        float4 av0 = *(const float4*)&Ab[(size_t)(m0 + arow) * K + k0 + acol];
        float4 av1 = *(const float4*)&Ab[(size_t)(m0 + arow) * K + k0 + acol + 4];
        As[acol + 0][arow] = av0.x;
        As[acol + 1][arow] = av0.y;
        As[acol + 2][arow] = av0.z;
        As[acol + 3][arow] = av0.w;
        As[acol + 4][arow] = av1.x;
        As[acol + 5][arow] = av1.y;
        As[acol + 6][arow] = av1.z;
        As[acol + 7][arow] = av1.w;
#pragma unroll
        for (int i = 0; i < 4; i++) {
            int f = tid + i * 128;
            int kk = f >> 5;                  // 0..15
            int c4 = (f & 31) * 4;            // 0..124
            *(float4*)&Bs[kk][c4] = *(const float4*)&Bb[(size_t)(k0 + kk) * NPIX + n0 + c4];
        }
        __syncthreads();
#pragma unroll
        for (int kk = 0; kk < 16; kk++) {
            float ra[8], rb[8];
            *(float4*)&ra[0] = *(const float4*)&As[kk][ty * 8];
            *(float4*)&ra[4] = *(const float4*)&As[kk][ty * 8 + 4];
            *(float4*)&rb[0] = *(const float4*)&Bs[kk][tx * 8];
            *(float4*)&rb[4] = *(const float4*)&Bs[kk][tx * 8 + 4];
#pragma unroll
            for (int i = 0; i < 8; i++)
#pragma unroll
                for (int j = 0; j < 8; j++) acc[i][j] += ra[i] * rb[j];
        }
        __syncthreads();
    }

#pragma unroll
    for (int i = 0; i < 8; i++) {
        int o = m0 + ty * 8 + i;
        float bo = bias[o];
        size_t base = (size_t)o * NPIX + n0 + tx * 8;
        float4 v0 = make_float4(acc[i][0] + bo, acc[i][1] + bo, acc[i][2] + bo, acc[i][3] + bo);
        float4 v1 = make_float4(acc[i][4] + bo, acc[i][5] + bo, acc[i][6] + bo, acc[i][7] + bo);
        *(float4*)&Cb[base] = v0;
        *(float4*)&Cb[base + 4] = v1;
    }
}

// ---------------- dw conv (3x3) + Gram/norm reduction + v write ----------------
// grid: (64 tiles of 16x16, HEADS, BATCH), 256 threads.
// 4 channel-plane "slots" (2 warps each); each thread computes a 1x4 output strip
// with float4 halo reads (6 LDS.128 + 36 FMA per 4 outputs).
#define DW_QS 0                      // 256*25 floats
#define DW_KS 6400                   // 256*25 floats
#define DW_HALO 12800                // 4 * 18 * 20 floats = 1440
#define DW_SMEM_FLOATS 14240         // * 4 = 56960 bytes

__global__ __launch_bounds__(256) void dw_gram_kernel(
    const float* __restrict__ w_dw, const float* __restrict__ b_dw)
{
    extern __shared__ float ds[];
    float* qs = ds + DW_QS;          // [pix 0..255][25]
    float* ks2 = ds + DW_KS;
    float* halo = ds + DW_HALO;      // [slot][18 rows][20 cols]

    const int b = blockIdx.z, h = blockIdx.y, tile = blockIdx.x;
    const int r0 = (tile >> 3) * 16, c0 = (tile & 7) * 16;
    const int tid = threadIdx.x;
    const int slot = tid >> 6;           // 0..3 (warp-uniform)
    const int s = tid & 63;
    const int sr = s >> 2;               // 0..15 output row
    const int sc = (s & 3) * 4;          // 0,4,8,12 output col base
    const size_t bq = (size_t)b * C3 * NPIX;

    for (int it = 0; it < 18; it++) {
        __syncthreads();                  // previous halo fully consumed
        // stage halos for 4 planes: plane pi = it*4 + p
        for (int t = tid; t < 4 * 324; t += 256) {
            int p = t / 324, e = t % 324;
            int hr = e / 18, hc = e % 18;
            int pi = it * 4 + p;
            int which = pi / 24, c = pi % 24;
            int ch = which * CDIM + h * CD + c;
            int Rg = r0 - 1 + hr, Cg = c0 - 1 + hc;
            float vv = 0.f;
            if (Rg >= 0 && Rg < HS && Cg >= 0 && Cg < WS)
                vv = g_qkv0[bq + (size_t)ch * NPIX + (size_t)Rg * WS + Cg];
            halo[p * 360 + hr * 20 + hc] = vv;
        }
        __syncthreads();

        const int pi = it * 4 + slot;
        const int which = pi / 24, c = pi % 24;
        const int ch = which * CDIM + h * CD + c;
        const float* wp = w_dw + ch * 9;
        const float* hp = halo + slot * 360;
        float bz = __ldg(&b_dw[ch]);
        float s0 = bz, s1 = bz, s2 = bz, s3 = bz;
#pragma unroll
        for (int r = 0; r < 3; r++) {
            float4 a = *(const float4*)(hp + (sr + r) * 20 + sc);
            float4 bv = *(const float4*)(hp + (sr + r) * 20 + sc + 4);
            float w0 = __ldg(&wp[r * 3 + 0]);
            float w1 = __ldg(&wp[r * 3 + 1]);
            float w2 = __ldg(&wp[r * 3 + 2]);
            s0 += a.x * w0 + a.y * w1 + a.z * w2;
            s1 += a.y * w0 + a.z * w1 + a.w * w2;
            s2 += a.z * w0 + a.w * w1 + bv.x * w2;
            s3 += a.w * w0 + bv.x * w1 + bv.y * w2;
        }
        const int p = sr * 16 + sc;
        if (which == 0) {
            qs[(p + 0) * 25 + c] = s0;
            qs[(p + 1) * 25 + c] = s1;
            qs[(p + 2) * 25 + c] = s2;
            qs[(p + 3) * 25 + c] = s3;
        } else if (which == 1) {
            ks2[(p + 0) * 25 + c] = s0;
            ks2[(p + 1) * 25 + c] = s1;
            ks2[(p + 2) * 25 + c] = s2;
            ks2[(p + 3) * 25 + c] = s3;
        } else {
            float* vp = g_v + (size_t)b * CDIM * NPIX + (size_t)(h * CD + c) * NPIX
                        + (size_t)(r0 + sr) * WS + (c0 + sc);
            *(float4*)vp = make_float4(s0, s1, s2, s3);
        }
    }
    __syncthreads();

    const int bh = b * HEADS + h;
    if (tid < 192) {
        const int cc = tid >> 3;
        const int db = (tid & 7) * 3;
        float a0 = 0.f, a1 = 0.f, a2 = 0.f;
        for (int p = 0; p < 256; p++) {
            float qv = qs[p * 25 + cc];
            a0 += qv * ks2[p * 25 + db];
            a1 += qv * ks2[p * 25 + db + 1];
            a2 += qv * ks2[p * 25 + db + 2];
        }
        float* Gp = g_G + (size_t)bh * CD * CD + cc * CD + db;
        atomicAdd(&Gp[0], a0);
        atomicAdd(&Gp[1], a1);
        atomicAdd(&Gp[2], a2);
    } else if (tid < 216) {
        const int c = tid - 192;
        float a = 0.f;
        for (int p = 0; p < 256; p++) { float qv = qs[p * 25 + c]; a += qv * qv; }
        atomicAdd(&g_QN[bh * CD + c], a);
    } else if (tid < 240) {
        const int c = tid - 216;
        float a = 0.f;
        for (int p = 0; p < 256; p++) { float kv = ks2[p * 25 + c]; a += kv * kv; }
        atomicAdd(&g_KN[bh * CD + c], a);
    }
}

// ---------------- attn: norms + 4x top-k sparse softmax via rank selection -> g_W ----------------
__global__ __launch_bounds__(32) void attn_kernel(
    const float* __restrict__ temp,
    const float* __restrict__ a1, const float* __restrict__ a2,
    const float* __restrict__ a3, const float* __restrict__ a4)
{
    const int bh = blockIdx.x;
    const int h = bh % HEADS;
    const int c = threadIdx.x;
    if (c >= CD) return;
    float attn[CD];
    float qn = fmaxf(sqrtf(g_QN[bh * CD + c]), 1e-12f);
    const float tmp = temp[h];
#pragma unroll
    for (int j = 0; j < CD; j++) {
        float kn = fmaxf(sqrtf(g_KN[bh * CD + j]), 1e-12f);
        attn[j] = g_G[(size_t)bh * CD * CD + c * CD + j] * tmp / (qn * kn);
    }
    float m = attn[0];
#pragma unroll
    for (int j = 1; j < CD; j++) m = fmaxf(m, attn[j]);
    // rank[j] = #{i : attn[i] > attn[j] || (attn[i]==attn[j] && i<j)}  (lax.top_k stable tie order)
    int rank[CD];
#pragma unroll
    for (int j = 0; j < CD; j++) {
        int r = 0;
#pragma unroll
        for (int i = 0; i < CD; i++) {
            bool gt = (attn[i] > attn[j]) || (attn[i] == attn[j] && i < j);
            r += gt ? 1 : 0;
        }
        rank[j] = r;
    }
    float e[CD];
    float sum0 = 0.f, sum1 = 0.f, sum2 = 0.f, sum3 = 0.f;
#pragma unroll
    for (int j = 0; j < CD; j++) {
        e[j] = expf(attn[j] - m);
        if (rank[j] < 12) sum0 += e[j];
        if (rank[j] < 16) sum1 += e[j];
        if (rank[j] < 18) sum2 += e[j];
        if (rank[j] < 19) sum3 += e[j];
    }
    const float r0 = a1[0] / sum0, r1 = a2[0] / sum1, r2 = a3[0] / sum2, r3 = a4[0] / sum3;
    float* Wp = g_W + (size_t)bh * CD * CD + c * CD;
#pragma unroll
    for (int j = 0; j < CD; j++) {
        float w = 0.f;
        if (rank[j] < 12) w += r0 * e[j];
        if (rank[j] < 16) w += r1 * e[j];
        if (rank[j] < 18) w += r2 * e[j];
        if (rank[j] < 19) w += r3 * e[j];
        Wp[j] = w;
    }
}

// ---------------- fold: M[b][o][h*24+d] = sum_c wproj[o][h*24+c] * W[b,h][c][d] ----------------
__global__ __launch_bounds__(256) void fold_kernel(const float* __restrict__ wproj)
{
    const int b = blockIdx.x, s = blockIdx.y;
    const int t = threadIdx.x;
    const int o = s * 32 + (t >> 3);
    const int hh = t & 7;
    const float* Wp = g_W + ((size_t)(b * HEADS + hh)) * CD * CD;
    float acc[CD];
#pragma unroll
    for (int d = 0; d < CD; d++) acc[d] = 0.f;
#pragma unroll
    for (int c = 0; c < CD; c++) {
        float w = __ldg(&wproj[o * CDIM + hh * CD + c]);
#pragma unroll
        for (int d = 0; d < CD; d++) acc[d] += w * __ldg(&Wp[c * CD + d]);
    }
    float* Mo = g_M + (size_t)b * CDIM * CDIM + (size_t)o * CDIM + hh * CD;
#pragma unroll
    for (int d = 0; d < CD; d++) Mo[d] = acc[d];
}

// ---------------- launch ----------------
extern "C" void kernel_launch(void* const* d_in, const int* in_sizes, int n_in,
                              void* d_out, int out_size)
{
    const float* x      = (const float*)d_in[0];
    const float* w_qkv  = (const float*)d_in[1];
    const float* b_qkv  = (const float*)d_in[2];
    const float* w_dw   = (const float*)d_in[3];
    const float* b_dw   = (const float*)d_in[4];
    const float* w_proj = (const float*)d_in[5];
    const float* b_proj = (const float*)d_in[6];
    const float* temp   = (const float*)d_in[7];
    const float* a1     = (const float*)d_in[8];
    const float* a2     = (const float*)d_in[9];
    const float* a3     = (const float*)d_in[10];
    const float* a4     = (const float*)d_in[11];
    float* out = (float*)d_out;

    cudaFuncSetAttribute(dw_gram_kernel, cudaFuncAttributeMaxDynamicSharedMemorySize, DW_SMEM_FLOATS * 4);

    init_stats_kernel<<<1, 256>>>();

    // qkv 1x1 conv: g_qkv0[b] = w_qkv @ x[b] + b_qkv   (576/64 = 9 m-tiles)
    gemm_kernel<0><<<dim3(NPIX / 128, C3 / 64, BATCH), 128>>>(w_qkv, x, b_qkv, nullptr);

    // dw conv + gram
    dw_gram_kernel<<<dim3(64, HEADS, BATCH), 256, DW_SMEM_FLOATS * 4>>>(w_dw, b_dw);

    // attention weights + fold
    attn_kernel<<<BATCH * HEADS, 32>>>(temp, a1, a2, a3, a4);
    fold_kernel<<<dim3(BATCH, 6), 256>>>(w_proj);

    // out[b] = g_M[b] @ g_v[b] + b_proj   (192/64 = 3 m-tiles)
    gemm_kernel<1><<<dim3(NPIX / 128, CDIM / 64, BATCH), 128>>>(nullptr, nullptr, b_proj, out);
}